// round 3
// baseline (speedup 1.0000x reference)
#include <cuda_runtime.h>
#include <cuda_fp16.h>
#include <cstdint>

// LoroSparseLinear fused kernel, R3.
// out = ((fp16(x) @ fp16(st24(w_in)*s_in).T) -> fp16 -> @ fp16(st24(w_out)*s_out).T + bias) / rank
//
// R3 changes vs R2 (L1tex was the 75% ceiling):
//  - cp.async (LDGSTS) for x (fp32) and both weight streams, double-buffered smem,
//    1 wait-group per iter, loads issued a full iteration ahead.
//  - GEMM1 warps = 2 M-groups x 4 K-groups: A read exactly once (built from fp32 smem
//    via LDS.64+cvt, conflict-free at stride 72 floats). 4-way K reduction via smem once.
//  - GEMM2 warps = 8 N-groups (warp tile 32x16): W-frags read exactly once;
//    A-frags (32 regs) loaded once for all 32 N-iters.

#define RANK 64
#define INF  4096
#define OUTF 4096
#define MTOT 8192
#define BM   32
#define BK   64
#define NK   (INF/BK)      // 64
#define BN2  128
#define NN   (OUTF/BN2)    // 32

// smem byte layout
#define XF_STRIDE  288     // 72 floats per x row
#define HB_STRIDE  144     // 72 halves per fp16 row
#define OFF_XF0    0
#define OFF_XF1    9216
#define OFF_B0     18432
#define OFF_B1     27648   // GEMM1 phase ends at 36864
#define OFF_XP     0       // 32 x 144 = 4608
#define OFF_SLAB   6144    // 6 slabs x 4096 = 24576, ends 30720 (reduction phase only)
#define OFF_W0     4608
#define OFF_W1     23040   // GEMM2 phase ends at 41472
#define SMEM_TOTAL 41472

__device__ __align__(16) __half g_sw_in[RANK * INF];    // (rank, in_f)  k-major
__device__ __align__(16) __half g_sw_out[OUTF * RANK];  // (out_f, rank) k-major

// ---------------------------------------------------------------------------
// Prep: 2:4 soft-threshold + scale + fp16 quantize for both weights.
// ---------------------------------------------------------------------------
__global__ void prep_kernel(const float* __restrict__ win, const float* __restrict__ wout,
                            const float* __restrict__ s_in, const float* __restrict__ s_out) {
    int g = blockIdx.x * blockDim.x + threadIdx.x;
    const int NGI = RANK * INF / 4;
    const int NGO = OUTF * RANK / 4;
    if (g >= NGI + NGO) return;
    const float4* src;
    __half* dst;
    float scale;
    int gi;
    if (g < NGI) { src = (const float4*)win;  dst = g_sw_in;  scale = *s_in;  gi = g; }
    else         { src = (const float4*)wout; dst = g_sw_out; scale = *s_out; gi = g - NGI; }
    float4 w = src[gi];
    float m0 = fabsf(w.x), m1 = fabsf(w.y), m2 = fabsf(w.z), m3 = fabsf(w.w);
    float lo1 = fminf(m0, m1), hi1 = fmaxf(m0, m1);
    float lo2 = fminf(m2, m3), hi2 = fmaxf(m2, m3);
    float t = fminf(fmaxf(lo1, lo2), fminf(hi1, hi2));
    float o0 = copysignf(fmaxf(m0 - t, 0.f), w.x) * scale;
    float o1 = copysignf(fmaxf(m1 - t, 0.f), w.y) * scale;
    float o2 = copysignf(fmaxf(m2 - t, 0.f), w.z) * scale;
    float o3 = copysignf(fmaxf(m3 - t, 0.f), w.w) * scale;
    __half2* d2 = (__half2*)(dst + gi * 4);
    d2[0] = __floats2half2_rn(o0, o1);
    d2[1] = __floats2half2_rn(o2, o3);
}

// ---------------------------------------------------------------------------
// PTX helpers
// ---------------------------------------------------------------------------
__device__ __forceinline__ uint32_t sptr(const void* p) {
    return (uint32_t)__cvta_generic_to_shared(p);
}
__device__ __forceinline__ void cp16(uint32_t dst, const void* src) {
    asm volatile("cp.async.cg.shared.global [%0], [%1], 16;" :: "r"(dst), "l"(src));
}
#define CP_COMMIT() asm volatile("cp.async.commit_group;")
#define CP_WAIT(n)  asm volatile("cp.async.wait_group %0;" :: "n"(n))

__device__ __forceinline__ void ldm4(uint32_t& r0, uint32_t& r1, uint32_t& r2, uint32_t& r3,
                                     uint32_t addr) {
    asm volatile("ldmatrix.sync.aligned.m8n8.x4.shared.b16 {%0,%1,%2,%3},[%4];"
                 : "=r"(r0), "=r"(r1), "=r"(r2), "=r"(r3) : "r"(addr));
}
__device__ __forceinline__ void mma16816(float c[4], uint32_t a0, uint32_t a1, uint32_t a2,
                                         uint32_t a3, uint32_t b0, uint32_t b1) {
    asm volatile(
        "mma.sync.aligned.m16n8k16.row.col.f32.f16.f16.f32 "
        "{%0,%1,%2,%3},{%4,%5,%6,%7},{%8,%9},{%0,%1,%2,%3};"
        : "+f"(c[0]), "+f"(c[1]), "+f"(c[2]), "+f"(c[3])
        : "r"(a0), "r"(a1), "r"(a2), "r"(a3), "r"(b0), "r"(b1));
}
__device__ __forceinline__ uint32_t packh2(float a, float b) {
    __half2 h = __floats2half2_rn(a, b);
    return *reinterpret_cast<uint32_t*>(&h);
}

// ---------------------------------------------------------------------------
// Fused main kernel. 256 threads (8 warps), 2 CTAs/SM.
// ---------------------------------------------------------------------------
__global__ void __launch_bounds__(256, 2)
loro_kernel(const float* __restrict__ x, const float* __restrict__ bias,
            float* __restrict__ out) {
    __shared__ __align__(16) char sm[SMEM_TOTAL];
    const int tid  = threadIdx.x;
    const int lane = tid & 31;
    const int wid  = tid >> 5;
    const int m0   = blockIdx.x * BM;
    const int mg   = wid & 1;   // GEMM1 M-group (16 rows)
    const int kg   = wid >> 1;  // GEMM1 K-group (16 of each 64-K chunk)
    const uint32_t smb = sptr(sm);

    // ---------------- GEMM1: xp = fp16(x) @ sw_in^T  (K split 4-way) ---------
    float c1[8][4] = {};   // warp tile: 16 rows x 64 rank-cols (partial K sums)

    // async issue of one K-chunk (x fp32 tile + w_in fp16 tile)
    auto issue1 = [&](int kb) {
        uint32_t xoff = (kb & 1) ? OFF_XF1 : OFF_XF0;
        uint32_t boff = (kb & 1) ? OFF_B1 : OFF_B0;
#pragma unroll
        for (int i = 0; i < 2; i++) {
            int c = tid + i * 256;                          // 512 chunks of 16B
            uint32_t dst = smb + xoff + (c >> 4) * XF_STRIDE + (c & 15) * 16;
            const float* src = x + (size_t)(m0 + (c >> 4)) * INF + kb * BK + (c & 15) * 4;
            cp16(dst, src);
        }
#pragma unroll
        for (int i = 0; i < 2; i++) {
            int c = tid + i * 256;                          // 512 chunks of 16B
            uint32_t dst = smb + boff + (c >> 3) * HB_STRIDE + (c & 7) * 16;
            const __half* src = g_sw_in + (size_t)(c >> 3) * INF + kb * BK + (c & 7) * 8;
            cp16(dst, src);
        }
    };

    issue1(0);
    CP_COMMIT();

    const int ar  = mg * 16 + (lane >> 2);          // A row for this thread
    const int ac  = kg * 16 + 2 * (lane & 3);       // A col (float index in chunk)
    const int bn  = (lane & 7) + ((lane >> 4) & 1) * 8;
    const int bc  = kg * 16 + ((lane >> 3) & 1) * 8;

    for (int kb = 0; kb < NK; kb++) {
        if (kb + 1 < NK) { issue1(kb + 1); CP_COMMIT(); CP_WAIT(1); }
        else             { CP_WAIT(0); }
        __syncthreads();

        const float*  xa = (const float*)(sm + ((kb & 1) ? OFF_XF1 : OFF_XF0));
        const __half* wb = (const __half*)(sm + ((kb & 1) ? OFF_B1 : OFF_B0));

        // build A fragment (16 rows x 16 k) from fp32 smem, fp16-quantized
        float2 v00 = *(const float2*)(xa + ar * 72 + ac);
        float2 v10 = *(const float2*)(xa + (ar + 8) * 72 + ac);
        float2 v01 = *(const float2*)(xa + ar * 72 + ac + 8);
        float2 v11 = *(const float2*)(xa + (ar + 8) * 72 + ac + 8);
        uint32_t a0 = packh2(v00.x, v00.y);
        uint32_t a1 = packh2(v10.x, v10.y);
        uint32_t a2 = packh2(v01.x, v01.y);
        uint32_t a3 = packh2(v11.x, v11.y);

#pragma unroll
        for (int j = 0; j < 4; j++) {                    // 4 n16 tiles over N=64
            uint32_t b0, b1, b2, b3;
            ldm4(b0, b1, b2, b3, sptr(wb + (j * 16 + bn) * 72 + bc));
            mma16816(c1[2 * j],     a0, a1, a2, a3, b0, b1);
            mma16816(c1[2 * j + 1], a0, a1, a2, a3, b2, b3);
        }
        __syncthreads();
    }

    // ---------------- 4-way K-group reduction + fp16 quantize of xp ----------
    {
        float* cf   = &c1[0][0];
        float* slab = (float*)(sm + OFF_SLAB);
        if (kg > 0) {
            float* p = slab + ((kg - 1) * 2 + mg) * 1024 + lane;
#pragma unroll
            for (int r2 = 0; r2 < 32; r2++) p[r2 * 32] = cf[r2];
        }
        __syncthreads();
        if (kg == 0) {
#pragma unroll
            for (int s = 0; s < 3; s++) {
                const float* p = slab + (s * 2 + mg) * 1024 + lane;
#pragma unroll
                for (int r2 = 0; r2 < 32; r2++) cf[r2] += p[r2 * 32];
            }
            __half* xp = (__half*)(sm + OFF_XP);
            int rr = mg * 16 + (lane >> 2);
            int cc = 2 * (lane & 3);
#pragma unroll
            for (int j = 0; j < 8; j++) {
                *(__half2*)(xp + rr * 72 + j * 8 + cc)       = __floats2half2_rn(c1[j][0], c1[j][1]);
                *(__half2*)(xp + (rr + 8) * 72 + j * 8 + cc) = __floats2half2_rn(c1[j][2], c1[j][3]);
            }
        }
        __syncthreads();
    }

    // ---------------- GEMM2: out = fp16(xp) @ sw_out^T + bias ----------------
    // A-frags: every warp holds all 32 rows x 64 k (32 regs), loaded once.
    const __half* xp = (const __half*)(sm + OFF_XP);
    uint32_t a2r[4][2][4];
#pragma unroll
    for (int ks = 0; ks < 4; ks++)
#pragma unroll
        for (int g = 0; g < 2; g++) {
            int rr = g * 16 + (lane & 7) + ((lane >> 3) & 1) * 8;
            int cc = ks * 16 + (lane >> 4) * 8;
            ldm4(a2r[ks][g][0], a2r[ks][g][1], a2r[ks][g][2], a2r[ks][g][3],
                 sptr(xp + rr * 72 + cc));
        }

    auto issue2 = [&](int nc) {
        uint32_t off = (nc & 1) ? OFF_W1 : OFF_W0;
#pragma unroll
        for (int i = 0; i < 4; i++) {
            int c = tid + i * 256;                          // 1024 chunks of 16B
            uint32_t dst = smb + off + (c >> 3) * HB_STRIDE + (c & 7) * 16;
            const __half* src = g_sw_out + (size_t)(nc * BN2 + (c >> 3)) * RANK + (c & 7) * 8;
            cp16(dst, src);
        }
    };

    issue2(0);
    CP_COMMIT();

    const int   ng   = wid;           // warp owns 16 of 128 out-cols per iter
    const float scal = 1.0f / RANK;

    for (int nc = 0; nc < NN; nc++) {
        if (nc + 1 < NN) { issue2(nc + 1); CP_COMMIT(); CP_WAIT(1); }
        else             { CP_WAIT(0); }
        __syncthreads();

        const __half* wsm = (const __half*)(sm + ((nc & 1) ? OFF_W1 : OFF_W0));
        float c2[2][2][4] = {};
#pragma unroll
        for (int ks = 0; ks < 4; ks++) {
            uint32_t b0, b1, b2, b3;
            ldm4(b0, b1, b2, b3,
                 sptr(wsm + (ng * 16 + bn) * 72 + ks * 16 + ((lane >> 3) & 1) * 8));
            mma16816(c2[0][0], a2r[ks][0][0], a2r[ks][0][1], a2r[ks][0][2], a2r[ks][0][3], b0, b1);
            mma16816(c2[0][1], a2r[ks][0][0], a2r[ks][0][1], a2r[ks][0][2], a2r[ks][0][3], b2, b3);
            mma16816(c2[1][0], a2r[ks][1][0], a2r[ks][1][1], a2r[ks][1][2], a2r[ks][1][3], b0, b1);
            mma16816(c2[1][1], a2r[ks][1][0], a2r[ks][1][1], a2r[ks][1][2], a2r[ks][1][3], b2, b3);
        }
        __syncthreads();   // buffer safe to overwrite next iter (epilogue is reg/gmem only)

        int colb = nc * BN2 + ng * 16 + 2 * (lane & 3);
        float2 bv0 = *(const float2*)(bias + colb);
        float2 bv1 = *(const float2*)(bias + colb + 8);
#pragma unroll
        for (int g = 0; g < 2; g++) {
            int row = m0 + g * 16 + (lane >> 2);
            float2 o;
            o.x = (c2[g][0][0] + bv0.x) * scal; o.y = (c2[g][0][1] + bv0.y) * scal;
            *(float2*)(out + (size_t)row * OUTF + colb) = o;
            o.x = (c2[g][0][2] + bv0.x) * scal; o.y = (c2[g][0][3] + bv0.y) * scal;
            *(float2*)(out + (size_t)(row + 8) * OUTF + colb) = o;
            o.x = (c2[g][1][0] + bv1.x) * scal; o.y = (c2[g][1][1] + bv1.y) * scal;
            *(float2*)(out + (size_t)row * OUTF + colb + 8) = o;
            o.x = (c2[g][1][2] + bv1.x) * scal; o.y = (c2[g][1][3] + bv1.y) * scal;
            *(float2*)(out + (size_t)(row + 8) * OUTF + colb + 8) = o;
        }
    }
}

// ---------------------------------------------------------------------------
extern "C" void kernel_launch(void* const* d_in, const int* in_sizes, int n_in,
                              void* d_out, int out_size) {
    const float* x     = (const float*)d_in[0];
    const float* win   = (const float*)d_in[1];
    const float* wout  = (const float*)d_in[2];
    const float* bias  = (const float*)d_in[3];
    const float* s_in  = (const float*)d_in[4];
    const float* s_out = (const float*)d_in[5];
    float* out = (float*)d_out;

    int ng = (RANK * INF + OUTF * RANK) / 4;
    prep_kernel<<<(ng + 255) / 256, 256>>>(win, wout, s_in, s_out);
    loro_kernel<<<MTOT / BM, 256>>>(x, bias, out);
}